// round 1
// baseline (speedup 1.0000x reference)
#include <cuda_runtime.h>
#include <cstdint>

#define BATCH 8
#define HEIGHT 256
#define WIDTH 256
#define HID 128
#define INC 6
#define OUTC 6

#define ROWJ 258   // x index j = x+1, with zero pads at j=0 and j=257

// Ping-pong intermediate activation buffers (NCHW fp32)
__device__ float g_buf1[(size_t)BATCH * HID * HEIGHT * WIDTH];
__device__ float g_buf2[(size_t)BATCH * HID * HEIGHT * WIDTH];

// ---------------------------------------------------------------------------
// Middle-style conv: IC -> 128 channels, 5-point cross stencil, optional ReLU.
// Block = (b, y). 256 threads = 8 warps. warp = oc-group (16 oc each),
// lane = px-group: thread owns px x = lane + 32*i, i in [0,8).
// ic staged through shared memory in chunks of CHUNK, with the chunk's weights.
// ---------------------------------------------------------------------------
template <int IC, int CHUNK, bool RELU>
__global__ void __launch_bounds__(256, 1)
conv_to128(const float* __restrict__ in, const float* __restrict__ wgt,
           const float* __restrict__ bias, float* __restrict__ out)
{
    extern __shared__ float sm[];
    float* ish = sm;                        // [CHUNK][3][ROWJ]
    float* wsh = sm + CHUNK * 3 * ROWJ;     // [CHUNK][128][5]

    const int b = blockIdx.x / HEIGHT;
    const int y = blockIdx.x % HEIGHT;
    const int lane = threadIdx.x & 31;
    const int warp = threadIdx.x >> 5;      // 0..7 -> oc group of 16

    float acc[16][8];
#pragma unroll
    for (int o = 0; o < 16; ++o)
#pragma unroll
        for (int i = 0; i < 8; ++i) acc[o][i] = 0.f;

    for (int c0 = 0; c0 < IC; c0 += CHUNK) {
        __syncthreads();
        // --- stage input rows y-1, y, y+1 for CHUNK channels (zero-padded) ---
        for (int idx = threadIdx.x; idx < CHUNK * 3 * ROWJ; idx += 256) {
            int icl = idx / (3 * ROWJ);
            int rem = idx - icl * (3 * ROWJ);
            int r = rem / ROWJ;
            int j = rem - r * ROWJ;
            int yy = y + r - 1;
            int xx = j - 1;
            float v = 0.f;
            if ((unsigned)yy < HEIGHT && (unsigned)xx < WIDTH)
                v = in[(((size_t)b * IC + (c0 + icl)) * HEIGHT + yy) * WIDTH + xx];
            ish[idx] = v;
        }
        // --- stage weights for this ic chunk: wsh[icl][oc][tap] ---
        for (int idx = threadIdx.x; idx < CHUNK * 128 * 5; idx += 256) {
            int icl = idx / (128 * 5);
            int rem = idx - icl * (128 * 5);
            int oc = rem / 5;
            int t = rem - oc * 5;
            wsh[idx] = wgt[((size_t)oc * IC + (c0 + icl)) * 5 + t];
        }
        __syncthreads();

#pragma unroll 1
        for (int icl = 0; icl < CHUNK; ++icl) {
            const float* rowb = &ish[icl * 3 * ROWJ];
            float top[8], cen[8], bot[8], lef[8], rig[8];
#pragma unroll
            for (int i = 0; i < 8; ++i) {
                int j = lane + 32 * i + 1;
                top[i] = rowb[j];
                cen[i] = rowb[ROWJ + j];
                bot[i] = rowb[2 * ROWJ + j];
                lef[i] = rowb[ROWJ + j - 1];
                rig[i] = rowb[ROWJ + j + 1];
            }
            const float* wp = &wsh[icl * 128 * 5 + (warp * 16) * 5];
#pragma unroll
            for (int o = 0; o < 16; ++o) {
                float w0 = wp[o * 5 + 0];
                float w1 = wp[o * 5 + 1];
                float w2 = wp[o * 5 + 2];
                float w3 = wp[o * 5 + 3];
                float w4 = wp[o * 5 + 4];
#pragma unroll
                for (int i = 0; i < 8; ++i) {
                    float s = acc[o][i];
                    s = fmaf(w0, cen[i], s);
                    s = fmaf(w1, top[i], s);
                    s = fmaf(w2, bot[i], s);
                    s = fmaf(w3, lef[i], s);
                    s = fmaf(w4, rig[i], s);
                    acc[o][i] = s;
                }
            }
        }
    }

    // --- epilogue: bias (+ReLU) and store ---
#pragma unroll
    for (int o = 0; o < 16; ++o) {
        int oc = warp * 16 + o;
        float bv = bias[oc];
#pragma unroll
        for (int i = 0; i < 8; ++i) {
            float v = acc[o][i] + bv;
            if (RELU) v = fmaxf(v, 0.f);
            out[(((size_t)b * 128 + oc) * HEIGHT + y) * WIDTH + lane + 32 * i] = v;
        }
    }
}

// ---------------------------------------------------------------------------
// Final layer: 128 -> 6 channels, no ReLU.
// Block covers an 8-row band: warp w handles row y0 + w. Thread: 6 oc x 8 px.
// ic chunked by 8 through smem (10 rows incl. halo). All weights preloaded.
// ---------------------------------------------------------------------------
__global__ void __launch_bounds__(256, 1)
conv_last(const float* __restrict__ in, const float* __restrict__ wgt,
          const float* __restrict__ bias, float* __restrict__ out)
{
    extern __shared__ float sm[];
    float* ish = sm;                   // [8][10][ROWJ]
    float* wsh = sm + 8 * 10 * ROWJ;   // [128][6][5] stored as ic*30 + oc*5 + t

    const int b = blockIdx.x / 32;
    const int y0 = (blockIdx.x % 32) * 8;
    const int lane = threadIdx.x & 31;
    const int warp = threadIdx.x >> 5;   // row within band
    const int y = y0 + warp;

    // preload all weights: wgt[oc*128*5 + ic*5 + t] -> wsh[ic*30 + oc*5 + t]
    for (int idx = threadIdx.x; idx < 128 * 6 * 5; idx += 256) {
        int ic = idx / 30;
        int rem = idx - ic * 30;
        int oc = rem / 5;
        int t = rem - oc * 5;
        wsh[idx] = wgt[((size_t)oc * 128 + ic) * 5 + t];
    }

    float acc[6][8];
#pragma unroll
    for (int o = 0; o < 6; ++o)
#pragma unroll
        for (int i = 0; i < 8; ++i) acc[o][i] = 0.f;

    for (int c0 = 0; c0 < 128; c0 += 8) {
        __syncthreads();
        // stage rows y0-1 .. y0+8 for 8 channels
        for (int idx = threadIdx.x; idx < 8 * 10 * ROWJ; idx += 256) {
            int icl = idx / (10 * ROWJ);
            int rem = idx - icl * (10 * ROWJ);
            int r = rem / ROWJ;
            int j = rem - r * ROWJ;
            int yy = y0 - 1 + r;
            int xx = j - 1;
            float v = 0.f;
            if ((unsigned)yy < HEIGHT && (unsigned)xx < WIDTH)
                v = in[(((size_t)b * 128 + (c0 + icl)) * HEIGHT + yy) * WIDTH + xx];
            ish[idx] = v;
        }
        __syncthreads();

#pragma unroll 1
        for (int icl = 0; icl < 8; ++icl) {
            // warp's rows within 10-row band: top = warp, cen = warp+1, bot = warp+2
            const float* rowb = &ish[icl * 10 * ROWJ + warp * ROWJ];
            float top[8], cen[8], bot[8], lef[8], rig[8];
#pragma unroll
            for (int i = 0; i < 8; ++i) {
                int j = lane + 32 * i + 1;
                top[i] = rowb[j];
                cen[i] = rowb[ROWJ + j];
                bot[i] = rowb[2 * ROWJ + j];
                lef[i] = rowb[ROWJ + j - 1];
                rig[i] = rowb[ROWJ + j + 1];
            }
            const float* wp = &wsh[(c0 + icl) * 30];
#pragma unroll
            for (int o = 0; o < 6; ++o) {
                float w0 = wp[o * 5 + 0];
                float w1 = wp[o * 5 + 1];
                float w2 = wp[o * 5 + 2];
                float w3 = wp[o * 5 + 3];
                float w4 = wp[o * 5 + 4];
#pragma unroll
                for (int i = 0; i < 8; ++i) {
                    float s = acc[o][i];
                    s = fmaf(w0, cen[i], s);
                    s = fmaf(w1, top[i], s);
                    s = fmaf(w2, bot[i], s);
                    s = fmaf(w3, lef[i], s);
                    s = fmaf(w4, rig[i], s);
                    acc[o][i] = s;
                }
            }
        }
    }

#pragma unroll
    for (int o = 0; o < 6; ++o) {
        float bv = bias[o];
#pragma unroll
        for (int i = 0; i < 8; ++i) {
            out[(((size_t)b * OUTC + o) * HEIGHT + y) * WIDTH + lane + 32 * i] =
                acc[o][i] + bv;
        }
    }
}

extern "C" void kernel_launch(void* const* d_in, const int* in_sizes, int n_in,
                              void* d_out, int out_size)
{
    const float* x  = (const float*)d_in[0];
    const float* w1 = (const float*)d_in[1];
    const float* b1 = (const float*)d_in[2];
    const float* w2 = (const float*)d_in[3];
    const float* b2 = (const float*)d_in[4];
    const float* w3 = (const float*)d_in[5];
    const float* b3 = (const float*)d_in[6];
    const float* w4 = (const float*)d_in[7];
    const float* b4 = (const float*)d_in[8];
    float* out = (float*)d_out;

    float *buf1, *buf2;
    cudaGetSymbolAddress((void**)&buf1, g_buf1);
    cudaGetSymbolAddress((void**)&buf2, g_buf2);

    const int smem1 = (INC * 3 * ROWJ + INC * 128 * 5) * 4;        // ~34 KB
    const int smem2 = (16 * 3 * ROWJ + 16 * 128 * 5) * 4;          // ~90.5 KB
    const int smem4 = (8 * 10 * ROWJ + 128 * 6 * 5) * 4;           // ~97.9 KB

    cudaFuncSetAttribute(conv_to128<INC, INC, true>,
                         cudaFuncAttributeMaxDynamicSharedMemorySize, smem1);
    cudaFuncSetAttribute(conv_to128<HID, 16, true>,
                         cudaFuncAttributeMaxDynamicSharedMemorySize, smem2);
    cudaFuncSetAttribute(conv_last,
                         cudaFuncAttributeMaxDynamicSharedMemorySize, smem4);

    dim3 grid_by(BATCH * HEIGHT);   // 2048
    dim3 grid_band(BATCH * (HEIGHT / 8));  // 256

    conv_to128<INC, INC, true><<<grid_by, 256, smem1>>>(x,    w1, b1, buf1);
    conv_to128<HID, 16,  true><<<grid_by, 256, smem2>>>(buf1, w2, b2, buf2);
    conv_to128<HID, 16,  true><<<grid_by, 256, smem2>>>(buf2, w3, b3, buf1);
    conv_last<<<grid_band, 256, smem4>>>(buf1, w4, b4, out);
}